// round 11
// baseline (speedup 1.0000x reference)
#include <cuda_runtime.h>
#include <math_constants.h>
#include <cstdint>

#define BATCH   4
#define N_UP    16384
#define N_DOWN  4096
#define C_UP    384
#define C_DOWN  512
#define C_OUT   512
#define KNN     3
#define EPSW    1e-8f

#define M_UP   (BATCH * N_UP)     // 65536
#define M_DN   (BATCH * N_DOWN)   // 16384

// ---------------- scratch (__device__ globals; no allocs allowed) ----------
__device__ float g_down_f[M_DN * C_OUT];                 // 32 MB fp32
__device__ int   g_idx[M_UP * KNN];
__device__ float g_w[M_UP * KNN];

__device__ unsigned short g_A_up[(size_t)M_UP * C_UP];      // fp16 up_features
__device__ unsigned short g_W_up16[(size_t)C_OUT * C_UP];   // fp16 W_up
__device__ unsigned short g_A_dn[(size_t)M_DN * C_DOWN];    // fp16 down_features
__device__ unsigned short g_W_dn16[(size_t)C_OUT * C_DOWN]; // fp16 W_down

// ---------------- helpers ---------------------------------------------------
static __device__ __forceinline__ uint32_t smem_u32(const void* p) {
    uint32_t a;
    asm("{ .reg .u64 t; cvta.to.shared.u64 t, %1; cvt.u32.u64 %0, t; }"
        : "=r"(a) : "l"(p));
    return a;
}
static __device__ __forceinline__ unsigned short f2h(float f) {
    unsigned short u;
    asm("cvt.rn.f16.f32 %0, %1;" : "=h"(u) : "f"(f));
    return u;
}
static __device__ __forceinline__ void cp16(uint32_t dst, const void* src) {
    asm volatile("cp.async.cg.shared.global [%0], [%1], 16;"
                 :: "r"(dst), "l"(src) : "memory");
}
static __device__ __forceinline__ void cp_commit() {
    asm volatile("cp.async.commit_group;" ::: "memory");
}
static __device__ __forceinline__ void cp_wait1() {
    asm volatile("cp.async.wait_group 1;" ::: "memory");
}
static __device__ __forceinline__ void ldmx4(uint32_t& r0, uint32_t& r1,
                                             uint32_t& r2, uint32_t& r3,
                                             uint32_t addr) {
    asm volatile("ldmatrix.sync.aligned.m8n8.x4.shared.b16 {%0,%1,%2,%3}, [%4];"
                 : "=r"(r0), "=r"(r1), "=r"(r2), "=r"(r3) : "r"(addr));
}
static __device__ __forceinline__ void mma16816(float* c, const uint32_t* a,
                                                uint32_t b0, uint32_t b1) {
    asm volatile(
        "mma.sync.aligned.m16n8k16.row.col.f32.f16.f16.f32 "
        "{%0,%1,%2,%3}, {%4,%5,%6,%7}, {%8,%9}, {%0,%1,%2,%3};"
        : "+f"(c[0]), "+f"(c[1]), "+f"(c[2]), "+f"(c[3])
        : "r"(a[0]), "r"(a[1]), "r"(a[2]), "r"(a[3]), "r"(b0), "r"(b1));
}

// ---------------- fp16 conversion -------------------------------------------
__global__ __launch_bounds__(256) void conv_f16(
    const float4* __restrict__ x, ushort4* __restrict__ h4, int n4)
{
    int i = blockIdx.x * 256 + threadIdx.x;
    if (i >= n4) return;
    float4 v = x[i];
    h4[i] = make_ushort4(f2h(v.x), f2h(v.y), f2h(v.z), f2h(v.w));
}

// ---------------------------------------------------------------------------
// fp16 GEMM via mma.sync: out[m,n] = sum_k A[m,k]*Wt[n,k] + bias[n]
// (+ KNN interpolation when FUSED).
// CTA 128x128, BK=64 fp16, 3-stage cp.async ring (issue 2 ahead, wait 1),
// 8 warps, warp tile 64x32, pitch-144 smem (conflict-free, ≡16 mod 128).
// ---------------------------------------------------------------------------
#define SM_PITCH 144
#define SM_HALF  (128 * SM_PITCH)            // 18432 bytes (A or B)
#define SM_STAGE (2 * SM_HALF)               // 36864 bytes
#define SM_TOTAL (3 * SM_STAGE)              // 110592 bytes
template<int K, bool FUSED>
__global__ __launch_bounds__(256) void gemm_f16(
    const unsigned short* __restrict__ Af,
    const unsigned short* __restrict__ Bf,
    const float* __restrict__ bias, float* __restrict__ outp)
{
    constexpr int NC = K / 64;
    extern __shared__ __align__(16) char smt[];
    const uint32_t sbase = smem_u32(smt);

    const int tid = threadIdx.x;
    const int lane = tid & 31;
    const int wid = tid >> 5;
    const int wm = wid >> 2;        // 0..1 -> m offset wm*64
    const int wn = wid & 3;         // 0..3 -> n offset wn*32
    const int m0 = blockIdx.y * 128;
    const int n0 = blockIdx.x * 128;

    // cp.async: per chunk, A needs 128 rows x 128B = 1024 x 16B; 256 threads
    // -> 4 slots each (one row, 64B half selected by tid&1), same for B.
    const int row = tid >> 1;       // 0..127
    const int h64 = (tid & 1) * 64; // byte offset in the 128B row half
    const int e32 = (tid & 1) * 32; // element offset (halfs)

    // ldmatrix per-lane offsets
    const int lq = lane >> 3, l7 = lane & 7;
    const int aRow = (lq & 1) * 8 + l7, aK = (lq >> 1) * 8;
    const int bRow = (lq >> 1) * 8 + l7, bK = (lq & 1) * 8;

    float acc[4][4][4];
#pragma unroll
    for (int i = 0; i < 4; i++)
#pragma unroll
        for (int j = 0; j < 4; j++)
#pragma unroll
            for (int r = 0; r < 4; r++) acc[i][j][r] = 0.0f;

    auto stage_of = [](int c) { return (c % 3); };

    auto issue = [&](int c) {
        if (c < NC) {
            const int kk = c * 64;
            const unsigned short* srcA = Af + (size_t)(m0 + row) * K + kk + e32;
            const unsigned short* srcB = Bf + (size_t)(n0 + row) * K + kk + e32;
            uint32_t dA = sbase + stage_of(c) * SM_STAGE + row * SM_PITCH + h64;
            uint32_t dB = dA + SM_HALF;
#pragma unroll
            for (int j = 0; j < 4; j++) {
                cp16(dA + j * 16, srcA + j * 8);
                cp16(dB + j * 16, srcB + j * 8);
            }
        }
        cp_commit();
    };

    issue(0); issue(1);

    for (int c = 0; c < NC; c++) {
        cp_wait1();
        __syncthreads();
        issue(c + 2);                 // overwrites stage (c-1)%3: safe past sync

        const uint32_t sA = sbase + stage_of(c) * SM_STAGE;
        const uint32_t sB = sA + SM_HALF;
#pragma unroll
        for (int ks = 0; ks < 4; ks++) {
            uint32_t a[4][4];
#pragma unroll
            for (int i = 0; i < 4; i++) {
                uint32_t addr = sA + (uint32_t)(wm * 64 + i * 16 + aRow) * SM_PITCH
                              + (uint32_t)(ks * 16 + aK) * 2;
                ldmx4(a[i][0], a[i][1], a[i][2], a[i][3], addr);
            }
            uint32_t b[4][2];
#pragma unroll
            for (int jp = 0; jp < 2; jp++) {
                uint32_t addr = sB + (uint32_t)(wn * 32 + jp * 16 + bRow) * SM_PITCH
                              + (uint32_t)(ks * 16 + bK) * 2;
                ldmx4(b[jp * 2][0], b[jp * 2][1], b[jp * 2 + 1][0], b[jp * 2 + 1][1], addr);
            }
#pragma unroll
            for (int i = 0; i < 4; i++)
#pragma unroll
                for (int j = 0; j < 4; j++)
                    mma16816(acc[i][j], a[i], b[j][0], b[j][1]);
        }
    }

    // ---------------- epilogue ----------------
    float* obase = FUSED ? outp : g_down_f;
#pragma unroll
    for (int i = 0; i < 4; i++) {
        const int r0 = m0 + wm * 64 + i * 16 + (lane >> 2);
        const int r1 = r0 + 8;
        const float* df0 = nullptr; const float* df1 = nullptr;
        int i00=0,i01=0,i02=0, i10=0,i11=0,i12=0;
        float w00=0,w01=0,w02=0, w10=0,w11=0,w12=0;
        if (FUSED) {
            df0 = g_down_f + (size_t)(r0 >> 14) * N_DOWN * C_OUT;
            df1 = g_down_f + (size_t)(r1 >> 14) * N_DOWN * C_OUT;
            int ib0 = r0 * KNN, ib1 = r1 * KNN;
            i00 = g_idx[ib0]; i01 = g_idx[ib0+1]; i02 = g_idx[ib0+2];
            w00 = g_w[ib0];   w01 = g_w[ib0+1];   w02 = g_w[ib0+2];
            i10 = g_idx[ib1]; i11 = g_idx[ib1+1]; i12 = g_idx[ib1+2];
            w10 = g_w[ib1];   w11 = g_w[ib1+1];   w12 = g_w[ib1+2];
        }
#pragma unroll
        for (int j = 0; j < 4; j++) {
            const int n = n0 + wn * 32 + j * 8 + (lane & 3) * 2;
            const float2 bi = *(const float2*)(bias + n);
            float2 o0, o1;
            o0.x = acc[i][j][0] + bi.x;  o0.y = acc[i][j][1] + bi.y;
            o1.x = acc[i][j][2] + bi.x;  o1.y = acc[i][j][3] + bi.y;
            if (FUSED) {
                float2 a0 = *(const float2*)(df0 + (size_t)i00 * C_OUT + n);
                float2 a1 = *(const float2*)(df0 + (size_t)i01 * C_OUT + n);
                float2 a2 = *(const float2*)(df0 + (size_t)i02 * C_OUT + n);
                o0.x += w00 * a0.x + w01 * a1.x + w02 * a2.x;
                o0.y += w00 * a0.y + w01 * a1.y + w02 * a2.y;
                float2 c0 = *(const float2*)(df1 + (size_t)i10 * C_OUT + n);
                float2 c1 = *(const float2*)(df1 + (size_t)i11 * C_OUT + n);
                float2 c2 = *(const float2*)(df1 + (size_t)i12 * C_OUT + n);
                o1.x += w10 * c0.x + w11 * c1.x + w12 * c2.x;
                o1.y += w10 * c0.y + w11 * c1.y + w12 * c2.y;
            }
            *(float2*)(obase + (size_t)r0 * C_OUT + n) = o0;
            *(float2*)(obase + (size_t)r1 * C_OUT + n) = o1;
        }
    }
}

// ---------------------------------------------------------------------------
// KNN: rank by t = d2 - 2*dot; strict-< insertion for stability.
// ---------------------------------------------------------------------------
__global__ __launch_bounds__(256) void knn_kernel(
    const float* __restrict__ up_points,
    const float* __restrict__ down_points)
{
    __shared__ float4 sp[2048];

    const int b = blockIdx.y;
    const int n = blockIdx.x * 256 + threadIdx.x;

    const float* up = up_points + (size_t)(b * N_UP + n) * 3;
    const float ux = up[0], uy = up[1], uz = up[2];
    const float u2 = ux * ux + uy * uy + uz * uz;
    const float a0 = -2.0f * ux, a1 = -2.0f * uy, a2 = -2.0f * uz;

    float bd0 = CUDART_INF_F, bd1 = CUDART_INF_F, bd2 = CUDART_INF_F;
    int   bi0 = 0, bi1 = 0, bi2 = 0;

    for (int phase = 0; phase < 2; phase++) {
        const int mbase = phase * 2048;
        __syncthreads();
        for (int i = threadIdx.x; i < 2048; i += 256) {
            const float* dp = down_points + (size_t)(b * N_DOWN + mbase + i) * 3;
            float x = dp[0], y = dp[1], z = dp[2];
            sp[i] = make_float4(x, y, z, x * x + y * y + z * z);
        }
        __syncthreads();

        for (int m = 0; m < 2048; m += 8) {
            float t[8];
#pragma unroll
            for (int j = 0; j < 8; j++) {
                float4 p = sp[m + j];
                t[j] = fmaf(a0, p.x, fmaf(a1, p.y, fmaf(a2, p.z, p.w)));
            }
            float mn = fminf(fminf(fminf(t[0], t[1]), fminf(t[2], t[3])),
                             fminf(fminf(t[4], t[5]), fminf(t[6], t[7])));
            if (mn < bd2) {
#pragma unroll
                for (int j = 0; j < 8; j++) {
                    float d = t[j];
                    if (d < bd2) {
                        int mi = mbase + m + j;
                        if (d < bd1) {
                            bd2 = bd1; bi2 = bi1;
                            if (d < bd0) { bd1 = bd0; bi1 = bi0; bd0 = d; bi0 = mi; }
                            else          { bd1 = d;  bi1 = mi; }
                        } else {
                            bd2 = d; bi2 = mi;
                        }
                    }
                }
            }
        }
    }

    float d0 = bd0 + u2, d1 = bd1 + u2, d2 = bd2 + u2;
    float w0 = 1.0f / (d0 + EPSW);
    float w1 = 1.0f / (d1 + EPSW);
    float w2 = 1.0f / (d2 + EPSW);
    float inv = 1.0f / (w0 + w1 + w2);

    const int base = (b * N_UP + n) * KNN;
    g_idx[base + 0] = bi0; g_idx[base + 1] = bi1; g_idx[base + 2] = bi2;
    g_w[base + 0] = w0 * inv; g_w[base + 1] = w1 * inv; g_w[base + 2] = w2 * inv;
}

// ---------------------------------------------------------------------------
extern "C" void kernel_launch(void* const* d_in, const int* in_sizes, int n_in,
                              void* d_out, int out_size) {
    (void)in_sizes; (void)n_in; (void)out_size;
    const float* up_points     = (const float*)d_in[0];
    const float* up_features   = (const float*)d_in[1];
    const float* down_points   = (const float*)d_in[2];
    const float* down_features = (const float*)d_in[3];
    const float* W_up          = (const float*)d_in[4];
    const float* b_up          = (const float*)d_in[5];
    const float* W_down        = (const float*)d_in[6];
    const float* b_down        = (const float*)d_in[7];
    float* out = (float*)d_out;

    void *pAU, *pWU, *pAD, *pWD;
    cudaGetSymbolAddress(&pAU, g_A_up);
    cudaGetSymbolAddress(&pWU, g_W_up16);
    cudaGetSymbolAddress(&pAD, g_A_dn);
    cudaGetSymbolAddress(&pWD, g_W_dn16);

    cudaFuncSetAttribute(gemm_f16<C_DOWN, false>,
                         cudaFuncAttributeMaxDynamicSharedMemorySize, SM_TOTAL);
    cudaFuncSetAttribute(gemm_f16<C_UP, true>,
                         cudaFuncAttributeMaxDynamicSharedMemorySize, SM_TOTAL);

    // conversions
    {
        int n4 = M_UP * C_UP / 4;
        conv_f16<<<(n4 + 255) / 256, 256>>>((const float4*)up_features,
                                            (ushort4*)pAU, n4);
    }
    {
        int n4 = C_OUT * C_UP / 4;
        conv_f16<<<(n4 + 255) / 256, 256>>>((const float4*)W_up, (ushort4*)pWU, n4);
    }
    {
        int n4 = M_DN * C_DOWN / 4;
        conv_f16<<<(n4 + 255) / 256, 256>>>((const float4*)down_features,
                                            (ushort4*)pAD, n4);
    }
    {
        int n4 = C_OUT * C_DOWN / 4;
        conv_f16<<<(n4 + 255) / 256, 256>>>((const float4*)W_down, (ushort4*)pWD, n4);
    }

    dim3 gk(N_UP / 256, BATCH);
    knn_kernel<<<gk, 256>>>(up_points, down_points);

    dim3 g1(C_OUT / 128, M_DN / 128);   // (4, 128)
    gemm_f16<C_DOWN, false><<<g1, 256, SM_TOTAL>>>(
        (const unsigned short*)pAD, (const unsigned short*)pWD, b_down, nullptr);

    dim3 g2(C_OUT / 128, M_UP / 128);   // (4, 512)
    gemm_f16<C_UP, true><<<g2, 256, SM_TOTAL>>>(
        (const unsigned short*)pAU, (const unsigned short*)pWU, b_up, out);
}

// round 15
// speedup vs baseline: 1.0649x; 1.0649x over previous
#include <cuda_runtime.h>
#include <math_constants.h>
#include <cstdint>

#define BATCH   4
#define N_UP    16384
#define N_DOWN  4096
#define C_UP    384
#define C_DOWN  512
#define C_OUT   512
#define KNN     3
#define EPSW    1e-8f

#define M_UP   (BATCH * N_UP)     // 65536
#define M_DN   (BATCH * N_DOWN)   // 16384

typedef unsigned short ushort_t;

// ---------------- scratch (__device__ globals; no allocs allowed) ----------
__device__ float g_down_f[M_DN * C_OUT];                 // 32 MB fp32
__device__ int   g_idx[M_UP * KNN];
__device__ float g_w[M_UP * KNN];

__device__ ushort_t g_A_up[(size_t)M_UP * C_UP];      // fp16 up_features
__device__ ushort_t g_W_up16[(size_t)C_OUT * C_UP];   // fp16 W_up
__device__ ushort_t g_A_dn[(size_t)M_DN * C_DOWN];    // fp16 down_features
__device__ ushort_t g_W_dn16[(size_t)C_OUT * C_DOWN]; // fp16 W_down

// ---------------- helpers ---------------------------------------------------
static __device__ __forceinline__ uint32_t smem_u32(const void* p) {
    uint32_t a;
    asm("{ .reg .u64 t; cvta.to.shared.u64 t, %1; cvt.u32.u64 %0, t; }"
        : "=r"(a) : "l"(p));
    return a;
}
static __device__ __forceinline__ ushort_t f2h(float f) {
    ushort_t u;
    asm("cvt.rn.f16.f32 %0, %1;" : "=h"(u) : "f"(f));
    return u;
}
static __device__ __forceinline__ void cp16(uint32_t dst, const void* src) {
    asm volatile("cp.async.cg.shared.global [%0], [%1], 16;"
                 :: "r"(dst), "l"(src) : "memory");
}
static __device__ __forceinline__ void cp_commit() {
    asm volatile("cp.async.commit_group;" ::: "memory");
}
static __device__ __forceinline__ void cp_wait2() {
    asm volatile("cp.async.wait_group 2;" ::: "memory");
}
static __device__ __forceinline__ void ldmx4(uint32_t& r0, uint32_t& r1,
                                             uint32_t& r2, uint32_t& r3,
                                             uint32_t addr) {
    asm volatile("ldmatrix.sync.aligned.m8n8.x4.shared.b16 {%0,%1,%2,%3}, [%4];"
                 : "=r"(r0), "=r"(r1), "=r"(r2), "=r"(r3) : "r"(addr));
}
static __device__ __forceinline__ void mma16816(float* c, const uint32_t* a,
                                                uint32_t b0, uint32_t b1) {
    asm volatile(
        "mma.sync.aligned.m16n8k16.row.col.f32.f16.f16.f32 "
        "{%0,%1,%2,%3}, {%4,%5,%6,%7}, {%8,%9}, {%0,%1,%2,%3};"
        : "+f"(c[0]), "+f"(c[1]), "+f"(c[2]), "+f"(c[3])
        : "r"(a[0]), "r"(a[1]), "r"(a[2]), "r"(a[3]), "r"(b0), "r"(b1));
}

// ---------------------------------------------------------------------------
// GEMM body (round-10 champion config): CTA 128x128, BK=32 fp16, 4-stage
// cp.async ring, 8 warps, warp tile 64x32, pitch-80 smem (conflict-free).
// ---------------------------------------------------------------------------
#define SM_STAGE 20480            // (128 rows * 80B) * 2 (A+B)
#define SM_TOTAL (4 * SM_STAGE)   // 81920

template<int K, bool FUSED>
static __device__ __forceinline__ void gemm_body(
    const ushort_t* __restrict__ Af,
    const ushort_t* __restrict__ Bf,
    const float* __restrict__ bias, float* __restrict__ outp,
    char* smt, int m0, int n0)
{
    constexpr int NC = K / 32;
    const uint32_t sbase = smem_u32(smt);

    const int tid = threadIdx.x;
    const int lane = tid & 31;
    const int wid = tid >> 5;
    const int wm = wid >> 2;        // 0..1 -> m offset wm*64
    const int wn = wid & 3;         // 0..3 -> n offset wn*32

    const int row = tid >> 2;
    const int q = tid & 3;

    const int lq = lane >> 3, l7 = lane & 7;
    const int aRow = (lq & 1) * 8 + l7, aK = (lq >> 1) * 8;
    const int bRow = (lq >> 1) * 8 + l7, bK = (lq & 1) * 8;

    float acc[4][4][4];
#pragma unroll
    for (int i = 0; i < 4; i++)
#pragma unroll
        for (int j = 0; j < 4; j++)
#pragma unroll
            for (int r = 0; r < 4; r++) acc[i][j][r] = 0.0f;

    auto issue = [&](int c) {
        if (c < NC) {
            const int kk = c * 32;
            const ushort_t* srcA = Af + (size_t)(m0 + row) * K + kk + q * 8;
            const ushort_t* srcB = Bf + (size_t)(n0 + row) * K + kk + q * 8;
            uint32_t dA = sbase + (c & 3) * SM_STAGE + row * 80 + q * 16;
            uint32_t dB = dA + 10240;
            cp16(dA, srcA);
            cp16(dA + 64 * 80, srcA + (size_t)64 * K);
            cp16(dB, srcB);
            cp16(dB + 64 * 80, srcB + (size_t)64 * K);
        }
        cp_commit();
    };

    issue(0); issue(1); issue(2);

    for (int c = 0; c < NC; c++) {
        cp_wait2();
        __syncthreads();
        issue(c + 3);

        const uint32_t sA = sbase + (c & 3) * SM_STAGE;
        const uint32_t sB = sA + 10240;
#pragma unroll
        for (int ks = 0; ks < 2; ks++) {
            uint32_t a[4][4];
#pragma unroll
            for (int i = 0; i < 4; i++) {
                uint32_t addr = sA + (uint32_t)(wm * 64 + i * 16 + aRow) * 80
                              + (uint32_t)(ks * 16 + aK) * 2;
                ldmx4(a[i][0], a[i][1], a[i][2], a[i][3], addr);
            }
            uint32_t b[4][2];
#pragma unroll
            for (int jp = 0; jp < 2; jp++) {
                uint32_t addr = sB + (uint32_t)(wn * 32 + jp * 16 + bRow) * 80
                              + (uint32_t)(ks * 16 + bK) * 2;
                ldmx4(b[jp * 2][0], b[jp * 2][1], b[jp * 2 + 1][0], b[jp * 2 + 1][1], addr);
            }
#pragma unroll
            for (int i = 0; i < 4; i++)
#pragma unroll
                for (int j = 0; j < 4; j++)
                    mma16816(acc[i][j], a[i], b[j][0], b[j][1]);
        }
    }

    float* obase = FUSED ? outp : g_down_f;
#pragma unroll
    for (int i = 0; i < 4; i++) {
        const int r0 = m0 + wm * 64 + i * 16 + (lane >> 2);
        const int r1 = r0 + 8;
        const float* df0 = nullptr; const float* df1 = nullptr;
        int i00=0,i01=0,i02=0, i10=0,i11=0,i12=0;
        float w00=0,w01=0,w02=0, w10=0,w11=0,w12=0;
        if (FUSED) {
            df0 = g_down_f + (size_t)(r0 >> 14) * N_DOWN * C_OUT;
            df1 = g_down_f + (size_t)(r1 >> 14) * N_DOWN * C_OUT;
            int ib0 = r0 * KNN, ib1 = r1 * KNN;
            i00 = g_idx[ib0]; i01 = g_idx[ib0+1]; i02 = g_idx[ib0+2];
            w00 = g_w[ib0];   w01 = g_w[ib0+1];   w02 = g_w[ib0+2];
            i10 = g_idx[ib1]; i11 = g_idx[ib1+1]; i12 = g_idx[ib1+2];
            w10 = g_w[ib1];   w11 = g_w[ib1+1];   w12 = g_w[ib1+2];
        }
#pragma unroll
        for (int j = 0; j < 4; j++) {
            const int n = n0 + wn * 32 + j * 8 + (lane & 3) * 2;
            const float2 bi = *(const float2*)(bias + n);
            float2 o0, o1;
            o0.x = acc[i][j][0] + bi.x;  o0.y = acc[i][j][1] + bi.y;
            o1.x = acc[i][j][2] + bi.x;  o1.y = acc[i][j][3] + bi.y;
            if (FUSED) {
                float2 a0 = *(const float2*)(df0 + (size_t)i00 * C_OUT + n);
                float2 a1 = *(const float2*)(df0 + (size_t)i01 * C_OUT + n);
                float2 a2 = *(const float2*)(df0 + (size_t)i02 * C_OUT + n);
                o0.x += w00 * a0.x + w01 * a1.x + w02 * a2.x;
                o0.y += w00 * a0.y + w01 * a1.y + w02 * a2.y;
                float2 c0 = *(const float2*)(df1 + (size_t)i10 * C_OUT + n);
                float2 c1 = *(const float2*)(df1 + (size_t)i11 * C_OUT + n);
                float2 c2 = *(const float2*)(df1 + (size_t)i12 * C_OUT + n);
                o1.x += w10 * c0.x + w11 * c1.x + w12 * c2.x;
                o1.y += w10 * c0.y + w11 * c1.y + w12 * c2.y;
            }
            *(float2*)(obase + (size_t)r0 * C_OUT + n) = o0;
            *(float2*)(obase + (size_t)r1 * C_OUT + n) = o1;
        }
    }
}

// ---------------------------------------------------------------------------
// KNN body: rank by t = d2 - 2*dot; strict-< insertion for stability.
// Uses first 32KB of dynamic smem.
// ---------------------------------------------------------------------------
static __device__ __forceinline__ void knn_body(
    int kb, char* smt,
    const float* __restrict__ up_points,
    const float* __restrict__ down_points)
{
    float4* sp = (float4*)smt;      // 2048 entries = 32 KB

    const int b = kb >> 6;          // batch 0..3
    const int n = (kb & 63) * 256 + threadIdx.x;

    const float* up = up_points + (size_t)(b * N_UP + n) * 3;
    const float ux = up[0], uy = up[1], uz = up[2];
    const float u2 = ux * ux + uy * uy + uz * uz;
    const float a0 = -2.0f * ux, a1 = -2.0f * uy, a2 = -2.0f * uz;

    float bd0 = CUDART_INF_F, bd1 = CUDART_INF_F, bd2 = CUDART_INF_F;
    int   bi0 = 0, bi1 = 0, bi2 = 0;

    for (int phase = 0; phase < 2; phase++) {
        const int mbase = phase * 2048;
        __syncthreads();
        for (int i = threadIdx.x; i < 2048; i += 256) {
            const float* dp = down_points + (size_t)(b * N_DOWN + mbase + i) * 3;
            float x = dp[0], y = dp[1], z = dp[2];
            sp[i] = make_float4(x, y, z, x * x + y * y + z * z);
        }
        __syncthreads();

        for (int m = 0; m < 2048; m += 8) {
            float t[8];
#pragma unroll
            for (int j = 0; j < 8; j++) {
                float4 p = sp[m + j];
                t[j] = fmaf(a0, p.x, fmaf(a1, p.y, fmaf(a2, p.z, p.w)));
            }
            float mn = fminf(fminf(fminf(t[0], t[1]), fminf(t[2], t[3])),
                             fminf(fminf(t[4], t[5]), fminf(t[6], t[7])));
            if (mn < bd2) {
#pragma unroll
                for (int j = 0; j < 8; j++) {
                    float d = t[j];
                    if (d < bd2) {
                        int mi = mbase + m + j;
                        if (d < bd1) {
                            bd2 = bd1; bi2 = bi1;
                            if (d < bd0) { bd1 = bd0; bi1 = bi0; bd0 = d; bi0 = mi; }
                            else          { bd1 = d;  bi1 = mi; }
                        } else {
                            bd2 = d; bi2 = mi;
                        }
                    }
                }
            }
        }
    }

    float d0 = bd0 + u2, d1 = bd1 + u2, d2 = bd2 + u2;
    float w0 = 1.0f / (d0 + EPSW);
    float w1 = 1.0f / (d1 + EPSW);
    float w2 = 1.0f / (d2 + EPSW);
    float inv = 1.0f / (w0 + w1 + w2);

    const int base = (b * N_UP + n) * KNN;
    g_idx[base + 0] = bi0; g_idx[base + 1] = bi1; g_idx[base + 2] = bi2;
    g_w[base + 0] = w0 * inv; g_w[base + 1] = w1 * inv; g_w[base + 2] = w2 * inv;
}

// ---------------------------------------------------------------------------
// Up-tensor fp16 conversion body (grid-stride over up_features and W_up)
// ---------------------------------------------------------------------------
#define N4A (M_UP * C_UP / 4)     // 6291456
#define N4W (C_OUT * C_UP / 4)    // 49152
static __device__ __forceinline__ void conv_up_body(
    int cb,
    const float4* __restrict__ upf4, const float4* __restrict__ wup4)
{
    ushort4* oa = (ushort4*)g_A_up;
    ushort4* ow = (ushort4*)g_W_up16;
    for (int i = cb * 256 + threadIdx.x; i < N4A + N4W; i += 256 * 256) {
        if (i < N4A) {
            float4 v = upf4[i];
            oa[i] = make_ushort4(f2h(v.x), f2h(v.y), f2h(v.z), f2h(v.w));
        } else {
            float4 v = wup4[i - N4A];
            ow[i - N4A] = make_ushort4(f2h(v.x), f2h(v.y), f2h(v.z), f2h(v.w));
        }
    }
}

// ---------------------------------------------------------------------------
// Down-tensor fp16 conversion (must precede the merged kernel)
// ---------------------------------------------------------------------------
#define N4AD (M_DN * C_DOWN / 4)  // 2097152
#define N4WD (C_OUT * C_DOWN / 4) // 65536
__global__ __launch_bounds__(256) void conv_dn_kernel(
    const float4* __restrict__ dnf4, const float4* __restrict__ wdn4)
{
    ushort4* oa = (ushort4*)g_A_dn;
    ushort4* ow = (ushort4*)g_W_dn16;
    int i = blockIdx.x * 256 + threadIdx.x;
    if (i < N4AD) {
        float4 v = dnf4[i];
        oa[i] = make_ushort4(f2h(v.x), f2h(v.y), f2h(v.z), f2h(v.w));
    } else if (i < N4AD + N4WD) {
        float4 v = wdn4[i - N4AD];
        ow[i - N4AD] = make_ushort4(f2h(v.x), f2h(v.y), f2h(v.z), f2h(v.w));
    }
}

// ---------------------------------------------------------------------------
// Merged kernel: interleaved block types (knn / conv_up / gemm1) so the block
// scheduler co-residents independent work.
//   blockIdx.x & 3 == 0 -> knn     (256 blocks)
//   blockIdx.x & 3 == 1 -> conv_up (256 blocks, grid-stride)
//   else                -> gemm1   (512 blocks)
// ---------------------------------------------------------------------------
__global__ __launch_bounds__(256) void merged_kernel(
    const float* __restrict__ up_points,
    const float* __restrict__ down_points,
    const float4* __restrict__ upf4, const float4* __restrict__ wup4,
    const float* __restrict__ b_down)
{
    extern __shared__ __align__(16) char smt[];
    const int bx = blockIdx.x;
    const int r = bx & 3;
    if (r == 0) {
        knn_body(bx >> 2, smt, up_points, down_points);
    } else if (r == 1) {
        conv_up_body(bx >> 2, upf4, wup4);
    } else {
        const int gb = (bx >> 2) * 2 + (r - 2);      // 0..511
        gemm_body<C_DOWN, false>(g_A_dn, g_W_dn16, b_down, nullptr, smt,
                                 (gb >> 2) * 128, (gb & 3) * 128);
    }
}

// ---------------------------------------------------------------------------
// Final fused GEMM (up features + interpolation)
// ---------------------------------------------------------------------------
__global__ __launch_bounds__(256) void gemm2_kernel(
    const float* __restrict__ bias, float* __restrict__ outp)
{
    extern __shared__ __align__(16) char smt[];
    gemm_body<C_UP, true>(g_A_up, g_W_up16, bias, outp, smt,
                          blockIdx.y * 128, blockIdx.x * 128);
}

// ---------------------------------------------------------------------------
extern "C" void kernel_launch(void* const* d_in, const int* in_sizes, int n_in,
                              void* d_out, int out_size) {
    (void)in_sizes; (void)n_in; (void)out_size;
    const float* up_points     = (const float*)d_in[0];
    const float* up_features   = (const float*)d_in[1];
    const float* down_points   = (const float*)d_in[2];
    const float* down_features = (const float*)d_in[3];
    const float* W_up          = (const float*)d_in[4];
    const float* b_up          = (const float*)d_in[5];
    const float* W_down        = (const float*)d_in[6];
    const float* b_down        = (const float*)d_in[7];
    float* out = (float*)d_out;

    cudaFuncSetAttribute(merged_kernel,
                         cudaFuncAttributeMaxDynamicSharedMemorySize, SM_TOTAL);
    cudaFuncSetAttribute(gemm2_kernel,
                         cudaFuncAttributeMaxDynamicSharedMemorySize, SM_TOTAL);

    // 1) down-side conversions (needed by gemm1 in the merged kernel)
    {
        int nblk = (N4AD + N4WD + 255) / 256;
        conv_dn_kernel<<<nblk, 256>>>((const float4*)down_features,
                                      (const float4*)W_down);
    }

    // 2) merged: knn + up-side conversions + gemm1, interleaved
    merged_kernel<<<1024, 256, SM_TOTAL>>>(
        up_points, down_points,
        (const float4*)up_features, (const float4*)W_up, b_down);

    // 3) fused output GEMM + interpolation
    dim3 g2(C_OUT / 128, M_UP / 128);   // (4, 512)
    gemm2_kernel<<<g2, 256, SM_TOTAL>>>(b_up, out);
}

// round 16
// speedup vs baseline: 1.1859x; 1.1136x over previous
#include <cuda_runtime.h>
#include <math_constants.h>
#include <cstdint>

#define BATCH   4
#define N_UP    16384
#define N_DOWN  4096
#define C_UP    384
#define C_DOWN  512
#define C_OUT   512
#define KNN     3
#define EPSW    1e-8f

#define M_UP   (BATCH * N_UP)     // 65536
#define M_DN   (BATCH * N_DOWN)   // 16384

typedef unsigned short ushort_t;

// ---------------- scratch (__device__ globals; no allocs allowed) ----------
__device__ float g_down_f[M_DN * C_OUT];                 // 32 MB fp32
__device__ int   g_idx[M_UP * KNN];
__device__ float g_w[M_UP * KNN];

__device__ ushort_t g_W_up16[(size_t)C_OUT * C_UP];   // fp16 W_up
__device__ ushort_t g_W_dn16[(size_t)C_OUT * C_DOWN]; // fp16 W_down

// ---------------- helpers ---------------------------------------------------
static __device__ __forceinline__ uint32_t smem_u32(const void* p) {
    uint32_t a;
    asm("{ .reg .u64 t; cvta.to.shared.u64 t, %1; cvt.u32.u64 %0, t; }"
        : "=r"(a) : "l"(p));
    return a;
}
static __device__ __forceinline__ ushort_t f2h(float f) {
    ushort_t u;
    asm("cvt.rn.f16.f32 %0, %1;" : "=h"(u) : "f"(f));
    return u;
}
// pack two fp32 -> fp16x2 (lo = b, hi = a), rn rounding (same as f2h per lane)
static __device__ __forceinline__ uint32_t f2h2(float hi, float lo) {
    uint32_t r;
    asm("cvt.rn.f16x2.f32 %0, %1, %2;" : "=r"(r) : "f"(hi), "f"(lo));
    return r;
}
static __device__ __forceinline__ void cp16(uint32_t dst, const void* src) {
    asm volatile("cp.async.cg.shared.global [%0], [%1], 16;"
                 :: "r"(dst), "l"(src) : "memory");
}
static __device__ __forceinline__ void cp_commit() {
    asm volatile("cp.async.commit_group;" ::: "memory");
}
static __device__ __forceinline__ void cp_wait2() {
    asm volatile("cp.async.wait_group 2;" ::: "memory");
}
static __device__ __forceinline__ void sts128(uint32_t addr, uint32_t r0,
                                              uint32_t r1, uint32_t r2, uint32_t r3) {
    asm volatile("st.shared.v4.b32 [%0], {%1,%2,%3,%4};"
                 :: "r"(addr), "r"(r0), "r"(r1), "r"(r2), "r"(r3) : "memory");
}
static __device__ __forceinline__ void ldmx4(uint32_t& r0, uint32_t& r1,
                                             uint32_t& r2, uint32_t& r3,
                                             uint32_t addr) {
    asm volatile("ldmatrix.sync.aligned.m8n8.x4.shared.b16 {%0,%1,%2,%3}, [%4];"
                 : "=r"(r0), "=r"(r1), "=r"(r2), "=r"(r3) : "r"(addr));
}
static __device__ __forceinline__ void mma16816(float* c, const uint32_t* a,
                                                uint32_t b0, uint32_t b1) {
    asm volatile(
        "mma.sync.aligned.m16n8k16.row.col.f32.f16.f16.f32 "
        "{%0,%1,%2,%3}, {%4,%5,%6,%7}, {%8,%9}, {%0,%1,%2,%3};"
        : "+f"(c[0]), "+f"(c[1]), "+f"(c[2]), "+f"(c[3])
        : "r"(a[0]), "r"(a[1]), "r"(a[2]), "r"(a[3]), "r"(b0), "r"(b1));
}

// ---------------- weight fp16 conversion (tiny) -----------------------------
#define N4WU (C_OUT * C_UP / 4)    // 49152
#define N4WD (C_OUT * C_DOWN / 4)  // 65536
__global__ __launch_bounds__(256) void conv_w_kernel(
    const float4* __restrict__ wup4, const float4* __restrict__ wdn4)
{
    ushort4* ou = (ushort4*)g_W_up16;
    ushort4* od = (ushort4*)g_W_dn16;
    int i = blockIdx.x * 256 + threadIdx.x;
    if (i < N4WU) {
        float4 v = wup4[i];
        ou[i] = make_ushort4(f2h(v.x), f2h(v.y), f2h(v.z), f2h(v.w));
    } else if (i < N4WU + N4WD) {
        float4 v = wdn4[i - N4WU];
        od[i - N4WU] = make_ushort4(f2h(v.x), f2h(v.y), f2h(v.z), f2h(v.w));
    }
}

// ---------------------------------------------------------------------------
// fp16 GEMM with in-kernel A conversion (fp32 -> fp16 at staging time):
//   out[m,n] = sum_k fp16(A[m,k]) * W16[n,k] + bias[n]  (+ interp when FUSED)
// CTA 128x128, BK=32, 8 warps, warp tile 64x32, pitch-80 smem.
// A: LDG fp32 (prefetched 1 chunk ahead) -> cvt.rn.f16x2 -> STS.
// B: 4-deep cp.async ring (weights pre-converted, tiny traffic).
// ---------------------------------------------------------------------------
#define SM_STAGE 20480            // (128 rows * 80B) * 2 (A+B regions)
#define SM_TOTAL (4 * SM_STAGE)   // 81920

template<int K, bool FUSED>
static __device__ __forceinline__ void gemm_body(
    const float* __restrict__ Af,        // fp32 activations [*, K]
    const ushort_t* __restrict__ Bf,     // fp16 weights [C_OUT, K]
    const float* __restrict__ bias, float* __restrict__ outp,
    char* smt, int m0, int n0)
{
    constexpr int NC = K / 32;
    const uint32_t sbase = smem_u32(smt);

    const int tid = threadIdx.x;
    const int lane = tid & 31;
    const int wid = tid >> 5;
    const int wm = wid >> 2;        // 0..1 -> m offset wm*64
    const int wn = wid & 3;         // 0..3 -> n offset wn*32

    const int row = tid >> 2;       // 0..63
    const int q = tid & 3;

    const int lq = lane >> 3, l7 = lane & 7;
    const int aRow = (lq & 1) * 8 + l7, aK = (lq >> 1) * 8;
    const int bRow = (lq >> 1) * 8 + l7, bK = (lq & 1) * 8;

    float acc[4][4][4];
#pragma unroll
    for (int i = 0; i < 4; i++)
#pragma unroll
        for (int j = 0; j < 4; j++)
#pragma unroll
            for (int r = 0; r < 4; r++) acc[i][j][r] = 0.0f;

    uint32_t rA[8];                 // packed fp16x2 for rows (row, row+64)

    auto loadA = [&](int c) {
        const float* s0 = Af + (size_t)(m0 + row) * K + c * 32 + q * 8;
        const float* s1 = Af + (size_t)(m0 + row + 64) * K + c * 32 + q * 8;
        float4 v0 = *(const float4*)s0;
        float4 v1 = *(const float4*)(s0 + 4);
        float4 v2 = *(const float4*)s1;
        float4 v3 = *(const float4*)(s1 + 4);
        rA[0] = f2h2(v0.y, v0.x); rA[1] = f2h2(v0.w, v0.z);
        rA[2] = f2h2(v1.y, v1.x); rA[3] = f2h2(v1.w, v1.z);
        rA[4] = f2h2(v2.y, v2.x); rA[5] = f2h2(v2.w, v2.z);
        rA[6] = f2h2(v3.y, v3.x); rA[7] = f2h2(v3.w, v3.z);
    };
    auto stsA = [&](int c) {
        uint32_t dA = sbase + (c & 3) * SM_STAGE + row * 80 + q * 16;
        sts128(dA, rA[0], rA[1], rA[2], rA[3]);
        sts128(dA + 64 * 80, rA[4], rA[5], rA[6], rA[7]);
    };
    auto issueB = [&](int c) {
        if (c < NC) {
            const ushort_t* srcB = Bf + (size_t)(n0 + row) * K + c * 32 + q * 8;
            uint32_t dB = sbase + (c & 3) * SM_STAGE + 10240 + row * 80 + q * 16;
            cp16(dB, srcB);
            cp16(dB + 64 * 80, srcB + (size_t)64 * K);
        }
        cp_commit();
    };

    loadA(0);
    issueB(0); issueB(1); issueB(2);

    for (int c = 0; c < NC; c++) {
        stsA(c);                    // stage c&3 A-region: last read at chunk c-4
        cp_wait2();                 // B(c) arrived
        __syncthreads();            // A visible + B stage-reuse safe
        issueB(c + 3);
        if (c + 1 < NC) loadA(c + 1);   // LDG latency hidden by compute(c)

        const uint32_t sA = sbase + (c & 3) * SM_STAGE;
        const uint32_t sB = sA + 10240;
#pragma unroll
        for (int ks = 0; ks < 2; ks++) {
            uint32_t a[4][4];
#pragma unroll
            for (int i = 0; i < 4; i++) {
                uint32_t addr = sA + (uint32_t)(wm * 64 + i * 16 + aRow) * 80
                              + (uint32_t)(ks * 16 + aK) * 2;
                ldmx4(a[i][0], a[i][1], a[i][2], a[i][3], addr);
            }
            uint32_t b[4][2];
#pragma unroll
            for (int jp = 0; jp < 2; jp++) {
                uint32_t addr = sB + (uint32_t)(wn * 32 + jp * 16 + bRow) * 80
                              + (uint32_t)(ks * 16 + bK) * 2;
                ldmx4(b[jp * 2][0], b[jp * 2][1], b[jp * 2 + 1][0], b[jp * 2 + 1][1], addr);
            }
#pragma unroll
            for (int i = 0; i < 4; i++)
#pragma unroll
                for (int j = 0; j < 4; j++)
                    mma16816(acc[i][j], a[i], b[j][0], b[j][1]);
        }
    }

    // ---------------- epilogue ----------------
    float* obase = FUSED ? outp : g_down_f;
#pragma unroll
    for (int i = 0; i < 4; i++) {
        const int r0 = m0 + wm * 64 + i * 16 + (lane >> 2);
        const int r1 = r0 + 8;
        const float* df0 = nullptr; const float* df1 = nullptr;
        int i00=0,i01=0,i02=0, i10=0,i11=0,i12=0;
        float w00=0,w01=0,w02=0, w10=0,w11=0,w12=0;
        if (FUSED) {
            df0 = g_down_f + (size_t)(r0 >> 14) * N_DOWN * C_OUT;
            df1 = g_down_f + (size_t)(r1 >> 14) * N_DOWN * C_OUT;
            int ib0 = r0 * KNN, ib1 = r1 * KNN;
            i00 = g_idx[ib0]; i01 = g_idx[ib0+1]; i02 = g_idx[ib0+2];
            w00 = g_w[ib0];   w01 = g_w[ib0+1];   w02 = g_w[ib0+2];
            i10 = g_idx[ib1]; i11 = g_idx[ib1+1]; i12 = g_idx[ib1+2];
            w10 = g_w[ib1];   w11 = g_w[ib1+1];   w12 = g_w[ib1+2];
        }
#pragma unroll
        for (int j = 0; j < 4; j++) {
            const int n = n0 + wn * 32 + j * 8 + (lane & 3) * 2;
            const float2 bi = *(const float2*)(bias + n);
            float2 o0, o1;
            o0.x = acc[i][j][0] + bi.x;  o0.y = acc[i][j][1] + bi.y;
            o1.x = acc[i][j][2] + bi.x;  o1.y = acc[i][j][3] + bi.y;
            if (FUSED) {
                float2 a0 = *(const float2*)(df0 + (size_t)i00 * C_OUT + n);
                float2 a1 = *(const float2*)(df0 + (size_t)i01 * C_OUT + n);
                float2 a2 = *(const float2*)(df0 + (size_t)i02 * C_OUT + n);
                o0.x += w00 * a0.x + w01 * a1.x + w02 * a2.x;
                o0.y += w00 * a0.y + w01 * a1.y + w02 * a2.y;
                float2 c0 = *(const float2*)(df1 + (size_t)i10 * C_OUT + n);
                float2 c1 = *(const float2*)(df1 + (size_t)i11 * C_OUT + n);
                float2 c2 = *(const float2*)(df1 + (size_t)i12 * C_OUT + n);
                o1.x += w10 * c0.x + w11 * c1.x + w12 * c2.x;
                o1.y += w10 * c0.y + w11 * c1.y + w12 * c2.y;
            }
            *(float2*)(obase + (size_t)r0 * C_OUT + n) = o0;
            *(float2*)(obase + (size_t)r1 * C_OUT + n) = o1;
        }
    }
}

__global__ __launch_bounds__(256) void gemm1_kernel(
    const float* __restrict__ A, const float* __restrict__ bias)
{
    extern __shared__ __align__(16) char smt[];
    gemm_body<C_DOWN, false>(A, g_W_dn16, bias, nullptr, smt,
                             blockIdx.y * 128, blockIdx.x * 128);
}
__global__ __launch_bounds__(256) void gemm2_kernel(
    const float* __restrict__ A, const float* __restrict__ bias,
    float* __restrict__ outp)
{
    extern __shared__ __align__(16) char smt[];
    gemm_body<C_UP, true>(A, g_W_up16, bias, outp, smt,
                          blockIdx.y * 128, blockIdx.x * 128);
}

// ---------------------------------------------------------------------------
// KNN: rank by t = d2 - 2*dot; strict-< insertion for stability.
// ---------------------------------------------------------------------------
__global__ __launch_bounds__(256) void knn_kernel(
    const float* __restrict__ up_points,
    const float* __restrict__ down_points)
{
    __shared__ float4 sp[2048];

    const int b = blockIdx.y;
    const int n = blockIdx.x * 256 + threadIdx.x;

    const float* up = up_points + (size_t)(b * N_UP + n) * 3;
    const float ux = up[0], uy = up[1], uz = up[2];
    const float u2 = ux * ux + uy * uy + uz * uz;
    const float a0 = -2.0f * ux, a1 = -2.0f * uy, a2 = -2.0f * uz;

    float bd0 = CUDART_INF_F, bd1 = CUDART_INF_F, bd2 = CUDART_INF_F;
    int   bi0 = 0, bi1 = 0, bi2 = 0;

    for (int phase = 0; phase < 2; phase++) {
        const int mbase = phase * 2048;
        __syncthreads();
        for (int i = threadIdx.x; i < 2048; i += 256) {
            const float* dp = down_points + (size_t)(b * N_DOWN + mbase + i) * 3;
            float x = dp[0], y = dp[1], z = dp[2];
            sp[i] = make_float4(x, y, z, x * x + y * y + z * z);
        }
        __syncthreads();

        for (int m = 0; m < 2048; m += 8) {
            float t[8];
#pragma unroll
            for (int j = 0; j < 8; j++) {
                float4 p = sp[m + j];
                t[j] = fmaf(a0, p.x, fmaf(a1, p.y, fmaf(a2, p.z, p.w)));
            }
            float mn = fminf(fminf(fminf(t[0], t[1]), fminf(t[2], t[3])),
                             fminf(fminf(t[4], t[5]), fminf(t[6], t[7])));
            if (mn < bd2) {
#pragma unroll
                for (int j = 0; j < 8; j++) {
                    float d = t[j];
                    if (d < bd2) {
                        int mi = mbase + m + j;
                        if (d < bd1) {
                            bd2 = bd1; bi2 = bi1;
                            if (d < bd0) { bd1 = bd0; bi1 = bi0; bd0 = d; bi0 = mi; }
                            else          { bd1 = d;  bi1 = mi; }
                        } else {
                            bd2 = d; bi2 = mi;
                        }
                    }
                }
            }
        }
    }

    float d0 = bd0 + u2, d1 = bd1 + u2, d2 = bd2 + u2;
    float w0 = 1.0f / (d0 + EPSW);
    float w1 = 1.0f / (d1 + EPSW);
    float w2 = 1.0f / (d2 + EPSW);
    float inv = 1.0f / (w0 + w1 + w2);

    const int base = (b * N_UP + n) * KNN;
    g_idx[base + 0] = bi0; g_idx[base + 1] = bi1; g_idx[base + 2] = bi2;
    g_w[base + 0] = w0 * inv; g_w[base + 1] = w1 * inv; g_w[base + 2] = w2 * inv;
}

// ---------------------------------------------------------------------------
extern "C" void kernel_launch(void* const* d_in, const int* in_sizes, int n_in,
                              void* d_out, int out_size) {
    (void)in_sizes; (void)n_in; (void)out_size;
    const float* up_points     = (const float*)d_in[0];
    const float* up_features   = (const float*)d_in[1];
    const float* down_points   = (const float*)d_in[2];
    const float* down_features = (const float*)d_in[3];
    const float* W_up          = (const float*)d_in[4];
    const float* b_up          = (const float*)d_in[5];
    const float* W_down        = (const float*)d_in[6];
    const float* b_down        = (const float*)d_in[7];
    float* out = (float*)d_out;

    cudaFuncSetAttribute(gemm1_kernel,
                         cudaFuncAttributeMaxDynamicSharedMemorySize, SM_TOTAL);
    cudaFuncSetAttribute(gemm2_kernel,
                         cudaFuncAttributeMaxDynamicSharedMemorySize, SM_TOTAL);

    // 1) weight conversions (tiny)
    {
        int nblk = (N4WU + N4WD + 255) / 256;
        conv_w_kernel<<<nblk, 256>>>((const float4*)W_up, (const float4*)W_down);
    }

    // 2) KNN (32KB static smem -> high occupancy)
    dim3 gk(N_UP / 256, BATCH);
    knn_kernel<<<gk, 256>>>(up_points, down_points);

    // 3) down GEMM (A = down_features fp32, converted in-kernel)
    dim3 g1(C_OUT / 128, M_DN / 128);   // (4, 128)
    gemm1_kernel<<<g1, 256, SM_TOTAL>>>(down_features, b_down);

    // 4) fused output GEMM + interpolation (A = up_features fp32)
    dim3 g2(C_OUT / 128, M_UP / 128);   // (4, 512)
    gemm2_kernel<<<g2, 256, SM_TOTAL>>>(up_features, b_up, out);
}

// round 17
// speedup vs baseline: 1.2146x; 1.0242x over previous
#include <cuda_runtime.h>
#include <math_constants.h>
#include <cstdint>

#define BATCH   4
#define N_UP    16384
#define N_DOWN  4096
#define C_UP    384
#define C_DOWN  512
#define C_OUT   512
#define KNN     3
#define EPSW    1e-8f

#define M_UP   (BATCH * N_UP)     // 65536
#define M_DN   (BATCH * N_DOWN)   // 16384

typedef unsigned short ushort_t;

// ---------------- scratch (__device__ globals; no allocs allowed) ----------
__device__ float g_down_f[M_DN * C_OUT];                 // 32 MB fp32
__device__ int   g_idx[M_UP * KNN];
__device__ float g_w[M_UP * KNN];

__device__ ushort_t g_W_up16[(size_t)C_OUT * C_UP];   // fp16 W_up
__device__ ushort_t g_W_dn16[(size_t)C_OUT * C_DOWN]; // fp16 W_down

// ---------------- helpers ---------------------------------------------------
static __device__ __forceinline__ uint32_t smem_u32(const void* p) {
    uint32_t a;
    asm("{ .reg .u64 t; cvta.to.shared.u64 t, %1; cvt.u32.u64 %0, t; }"
        : "=r"(a) : "l"(p));
    return a;
}
static __device__ __forceinline__ ushort_t f2h(float f) {
    ushort_t u;
    asm("cvt.rn.f16.f32 %0, %1;" : "=h"(u) : "f"(f));
    return u;
}
static __device__ __forceinline__ uint32_t f2h2(float hi, float lo) {
    uint32_t r;
    asm("cvt.rn.f16x2.f32 %0, %1, %2;" : "=r"(r) : "f"(hi), "f"(lo));
    return r;
}
static __device__ __forceinline__ void cp16(uint32_t dst, const void* src) {
    asm volatile("cp.async.cg.shared.global [%0], [%1], 16;"
                 :: "r"(dst), "l"(src) : "memory");
}
static __device__ __forceinline__ void cp_commit() {
    asm volatile("cp.async.commit_group;" ::: "memory");
}
static __device__ __forceinline__ void cp_wait2() {
    asm volatile("cp.async.wait_group 2;" ::: "memory");
}
static __device__ __forceinline__ void sts128(uint32_t addr, uint32_t r0,
                                              uint32_t r1, uint32_t r2, uint32_t r3) {
    asm volatile("st.shared.v4.b32 [%0], {%1,%2,%3,%4};"
                 :: "r"(addr), "r"(r0), "r"(r1), "r"(r2), "r"(r3) : "memory");
}
static __device__ __forceinline__ void ldmx4(uint32_t& r0, uint32_t& r1,
                                             uint32_t& r2, uint32_t& r3,
                                             uint32_t addr) {
    asm volatile("ldmatrix.sync.aligned.m8n8.x4.shared.b16 {%0,%1,%2,%3}, [%4];"
                 : "=r"(r0), "=r"(r1), "=r"(r2), "=r"(r3) : "r"(addr));
}
static __device__ __forceinline__ void mma16816(float* c, const uint32_t* a,
                                                uint32_t b0, uint32_t b1) {
    asm volatile(
        "mma.sync.aligned.m16n8k16.row.col.f32.f16.f16.f32 "
        "{%0,%1,%2,%3}, {%4,%5,%6,%7}, {%8,%9}, {%0,%1,%2,%3};"
        : "+f"(c[0]), "+f"(c[1]), "+f"(c[2]), "+f"(c[3])
        : "r"(a[0]), "r"(a[1]), "r"(a[2]), "r"(a[3]), "r"(b0), "r"(b1));
}

// ---------------- weight fp16 conversion (tiny) -----------------------------
#define N4WU (C_OUT * C_UP / 4)    // 49152
#define N4WD (C_OUT * C_DOWN / 4)  // 65536
__global__ __launch_bounds__(256) void conv_w_kernel(
    const float4* __restrict__ wup4, const float4* __restrict__ wdn4)
{
    ushort4* ou = (ushort4*)g_W_up16;
    ushort4* od = (ushort4*)g_W_dn16;
    int i = blockIdx.x * 256 + threadIdx.x;
    if (i < N4WU) {
        float4 v = wup4[i];
        ou[i] = make_ushort4(f2h(v.x), f2h(v.y), f2h(v.z), f2h(v.w));
    } else if (i < N4WU + N4WD) {
        float4 v = wdn4[i - N4WU];
        od[i - N4WU] = make_ushort4(f2h(v.x), f2h(v.y), f2h(v.z), f2h(v.w));
    }
}

// ---------------------------------------------------------------------------
// fp16 GEMM, in-kernel A conversion, fragment-software-pipelined mainloop.
// CTA 128x128, BK=32, 8 warps, warp tile 64x32, pitch-80 smem, 4-stage B ring.
// ---------------------------------------------------------------------------
#define SM_STAGE 20480            // (128 rows * 80B) * 2 (A+B regions)
#define SM_TOTAL (4 * SM_STAGE)   // 81920

template<int K, bool FUSED>
static __device__ __forceinline__ void gemm_body(
    const float* __restrict__ Af,        // fp32 activations [*, K]
    const ushort_t* __restrict__ Bf,     // fp16 weights [C_OUT, K]
    const float* __restrict__ bias, float* __restrict__ outp,
    char* smt, int m0, int n0)
{
    constexpr int NC = K / 32;
    const uint32_t sbase = smem_u32(smt);

    const int tid = threadIdx.x;
    const int lane = tid & 31;
    const int wid = tid >> 5;
    const int wm = wid >> 2;        // 0..1 -> m offset wm*64
    const int wn = wid & 3;         // 0..3 -> n offset wn*32

    const int row = tid >> 2;       // 0..63
    const int q = tid & 3;

    const int lq = lane >> 3, l7 = lane & 7;
    const int aRow = (lq & 1) * 8 + l7, aK = (lq >> 1) * 8;
    const int bRow = (lq >> 1) * 8 + l7, bK = (lq & 1) * 8;

    float acc[4][4][4];
#pragma unroll
    for (int i = 0; i < 4; i++)
#pragma unroll
        for (int j = 0; j < 4; j++)
#pragma unroll
            for (int r = 0; r < 4; r++) acc[i][j][r] = 0.0f;

    uint32_t rA[8];                 // packed fp16x2 for rows (row, row+64)

    auto loadA = [&](int c) {
        const float* s0 = Af + (size_t)(m0 + row) * K + c * 32 + q * 8;
        const float* s1 = Af + (size_t)(m0 + row + 64) * K + c * 32 + q * 8;
        float4 v0 = *(const float4*)s0;
        float4 v1 = *(const float4*)(s0 + 4);
        float4 v2 = *(const float4*)s1;
        float4 v3 = *(const float4*)(s1 + 4);
        rA[0] = f2h2(v0.y, v0.x); rA[1] = f2h2(v0.w, v0.z);
        rA[2] = f2h2(v1.y, v1.x); rA[3] = f2h2(v1.w, v1.z);
        rA[4] = f2h2(v2.y, v2.x); rA[5] = f2h2(v2.w, v2.z);
        rA[6] = f2h2(v3.y, v3.x); rA[7] = f2h2(v3.w, v3.z);
    };
    auto stsA = [&](int c) {
        uint32_t dA = sbase + (c & 3) * SM_STAGE + row * 80 + q * 16;
        sts128(dA, rA[0], rA[1], rA[2], rA[3]);
        sts128(dA + 64 * 80, rA[4], rA[5], rA[6], rA[7]);
    };
    auto issueB = [&](int c) {
        if (c < NC) {
            const ushort_t* srcB = Bf + (size_t)(n0 + row) * K + c * 32 + q * 8;
            uint32_t dB = sbase + (c & 3) * SM_STAGE + 10240 + row * 80 + q * 16;
            cp16(dB, srcB);
            cp16(dB + 64 * 80, srcB + (size_t)64 * K);
        }
        cp_commit();
    };

    loadA(0);
    issueB(0); issueB(1); issueB(2);

    for (int c = 0; c < NC; c++) {
        stsA(c);
        cp_wait2();
        __syncthreads();
        issueB(c + 3);
        if (c + 1 < NC) loadA(c + 1);

        const uint32_t sA = sbase + (c & 3) * SM_STAGE;
        const uint32_t sB = sA + 10240;

        // ---- fragment software pipeline over the 2 ks steps ----
        uint32_t a[4][4];            // A frags, reused ks0 -> ks1
        uint32_t b0[4][2], b1[4][2]; // B frags for ks0 and ks1

        // preload: B for both ks (4 LDSM) + A ks0 (4 LDSM) — all independent
#pragma unroll
        for (int jp = 0; jp < 2; jp++) {
            uint32_t ab0 = sB + (uint32_t)(wn * 32 + jp * 16 + bRow) * 80
                         + (uint32_t)(bK) * 2;
            ldmx4(b0[jp * 2][0], b0[jp * 2][1], b0[jp * 2 + 1][0], b0[jp * 2 + 1][1], ab0);
            uint32_t ab1 = ab0 + 16 * 2;
            ldmx4(b1[jp * 2][0], b1[jp * 2][1], b1[jp * 2 + 1][0], b1[jp * 2 + 1][1], ab1);
        }
#pragma unroll
        for (int i = 0; i < 4; i++) {
            uint32_t addr = sA + (uint32_t)(wm * 64 + i * 16 + aRow) * 80
                          + (uint32_t)(aK) * 2;
            ldmx4(a[i][0], a[i][1], a[i][2], a[i][3], addr);
        }

        // ks0 MMAs; refill a[i] with its ks1 fragment right after last use
#pragma unroll
        for (int i = 0; i < 4; i++) {
#pragma unroll
            for (int j = 0; j < 4; j++)
                mma16816(acc[i][j], a[i], b0[j][0], b0[j][1]);
            uint32_t addr = sA + (uint32_t)(wm * 64 + i * 16 + aRow) * 80
                          + (uint32_t)(16 + aK) * 2;
            ldmx4(a[i][0], a[i][1], a[i][2], a[i][3], addr);
        }
        // ks1 MMAs — fragments already in flight/ready
#pragma unroll
        for (int i = 0; i < 4; i++)
#pragma unroll
            for (int j = 0; j < 4; j++)
                mma16816(acc[i][j], a[i], b1[j][0], b1[j][1]);
    }

    // ---------------- epilogue ----------------
    float* obase = FUSED ? outp : g_down_f;
#pragma unroll
    for (int i = 0; i < 4; i++) {
        const int r0 = m0 + wm * 64 + i * 16 + (lane >> 2);
        const int r1 = r0 + 8;
        const float* df0 = nullptr; const float* df1 = nullptr;
        int i00=0,i01=0,i02=0, i10=0,i11=0,i12=0;
        float w00=0,w01=0,w02=0, w10=0,w11=0,w12=0;
        if (FUSED) {
            df0 = g_down_f + (size_t)(r0 >> 14) * N_DOWN * C_OUT;
            df1 = g_down_f + (size_t)(r1 >> 14) * N_DOWN * C_OUT;
            int ib0 = r0 * KNN, ib1 = r1 * KNN;
            i00 = g_idx[ib0]; i01 = g_idx[ib0+1]; i02 = g_idx[ib0+2];
            w00 = g_w[ib0];   w01 = g_w[ib0+1];   w02 = g_w[ib0+2];
            i10 = g_idx[ib1]; i11 = g_idx[ib1+1]; i12 = g_idx[ib1+2];
            w10 = g_w[ib1];   w11 = g_w[ib1+1];   w12 = g_w[ib1+2];
        }
#pragma unroll
        for (int j = 0; j < 4; j++) {
            const int n = n0 + wn * 32 + j * 8 + (lane & 3) * 2;
            const float2 bi = *(const float2*)(bias + n);
            float2 o0, o1;
            o0.x = acc[i][j][0] + bi.x;  o0.y = acc[i][j][1] + bi.y;
            o1.x = acc[i][j][2] + bi.x;  o1.y = acc[i][j][3] + bi.y;
            if (FUSED) {
                float2 a0 = *(const float2*)(df0 + (size_t)i00 * C_OUT + n);
                float2 a1 = *(const float2*)(df0 + (size_t)i01 * C_OUT + n);
                float2 a2 = *(const float2*)(df0 + (size_t)i02 * C_OUT + n);
                o0.x += w00 * a0.x + w01 * a1.x + w02 * a2.x;
                o0.y += w00 * a0.y + w01 * a1.y + w02 * a2.y;
                float2 c0 = *(const float2*)(df1 + (size_t)i10 * C_OUT + n);
                float2 c1 = *(const float2*)(df1 + (size_t)i11 * C_OUT + n);
                float2 c2 = *(const float2*)(df1 + (size_t)i12 * C_OUT + n);
                o1.x += w10 * c0.x + w11 * c1.x + w12 * c2.x;
                o1.y += w10 * c0.y + w11 * c1.y + w12 * c2.y;
            }
            *(float2*)(obase + (size_t)r0 * C_OUT + n) = o0;
            *(float2*)(obase + (size_t)r1 * C_OUT + n) = o1;
        }
    }
}

__global__ __launch_bounds__(256) void gemm1_kernel(
    const float* __restrict__ A, const float* __restrict__ bias)
{
    extern __shared__ __align__(16) char smt[];
    gemm_body<C_DOWN, false>(A, g_W_dn16, bias, nullptr, smt,
                             blockIdx.y * 128, blockIdx.x * 128);
}
__global__ __launch_bounds__(256) void gemm2_kernel(
    const float* __restrict__ A, const float* __restrict__ bias,
    float* __restrict__ outp)
{
    extern __shared__ __align__(16) char smt[];
    gemm_body<C_UP, true>(A, g_W_up16, bias, outp, smt,
                          blockIdx.y * 128, blockIdx.x * 128);
}

// ---------------------------------------------------------------------------
// KNN: rank by t = d2 - 2*dot; strict-< insertion for stability.
// ---------------------------------------------------------------------------
__global__ __launch_bounds__(256) void knn_kernel(
    const float* __restrict__ up_points,
    const float* __restrict__ down_points)
{
    __shared__ float4 sp[2048];

    const int b = blockIdx.y;
    const int n = blockIdx.x * 256 + threadIdx.x;

    const float* up = up_points + (size_t)(b * N_UP + n) * 3;
    const float ux = up[0], uy = up[1], uz = up[2];
    const float u2 = ux * ux + uy * uy + uz * uz;
    const float a0 = -2.0f * ux, a1 = -2.0f * uy, a2 = -2.0f * uz;

    float bd0 = CUDART_INF_F, bd1 = CUDART_INF_F, bd2 = CUDART_INF_F;
    int   bi0 = 0, bi1 = 0, bi2 = 0;

    for (int phase = 0; phase < 2; phase++) {
        const int mbase = phase * 2048;
        __syncthreads();
        for (int i = threadIdx.x; i < 2048; i += 256) {
            const float* dp = down_points + (size_t)(b * N_DOWN + mbase + i) * 3;
            float x = dp[0], y = dp[1], z = dp[2];
            sp[i] = make_float4(x, y, z, x * x + y * y + z * z);
        }
        __syncthreads();

        for (int m = 0; m < 2048; m += 8) {
            float t[8];
#pragma unroll
            for (int j = 0; j < 8; j++) {
                float4 p = sp[m + j];
                t[j] = fmaf(a0, p.x, fmaf(a1, p.y, fmaf(a2, p.z, p.w)));
            }
            float mn = fminf(fminf(fminf(t[0], t[1]), fminf(t[2], t[3])),
                             fminf(fminf(t[4], t[5]), fminf(t[6], t[7])));
            if (mn < bd2) {
#pragma unroll
                for (int j = 0; j < 8; j++) {
                    float d = t[j];
                    if (d < bd2) {
                        int mi = mbase + m + j;
                        if (d < bd1) {
                            bd2 = bd1; bi2 = bi1;
                            if (d < bd0) { bd1 = bd0; bi1 = bi0; bd0 = d; bi0 = mi; }
                            else          { bd1 = d;  bi1 = mi; }
                        } else {
                            bd2 = d; bi2 = mi;
                        }
                    }
                }
            }
        }
    }

    float d0 = bd0 + u2, d1 = bd1 + u2, d2 = bd2 + u2;
    float w0 = 1.0f / (d0 + EPSW);
    float w1 = 1.0f / (d1 + EPSW);
    float w2 = 1.0f / (d2 + EPSW);
    float inv = 1.0f / (w0 + w1 + w2);

    const int base = (b * N_UP + n) * KNN;
    g_idx[base + 0] = bi0; g_idx[base + 1] = bi1; g_idx[base + 2] = bi2;
    g_w[base + 0] = w0 * inv; g_w[base + 1] = w1 * inv; g_w[base + 2] = w2 * inv;
}

// ---------------------------------------------------------------------------
extern "C" void kernel_launch(void* const* d_in, const int* in_sizes, int n_in,
                              void* d_out, int out_size) {
    (void)in_sizes; (void)n_in; (void)out_size;
    const float* up_points     = (const float*)d_in[0];
    const float* up_features   = (const float*)d_in[1];
    const float* down_points   = (const float*)d_in[2];
    const float* down_features = (const float*)d_in[3];
    const float* W_up          = (const float*)d_in[4];
    const float* b_up          = (const float*)d_in[5];
    const float* W_down        = (const float*)d_in[6];
    const float* b_down        = (const float*)d_in[7];
    float* out = (float*)d_out;

    cudaFuncSetAttribute(gemm1_kernel,
                         cudaFuncAttributeMaxDynamicSharedMemorySize, SM_TOTAL);
    cudaFuncSetAttribute(gemm2_kernel,
                         cudaFuncAttributeMaxDynamicSharedMemorySize, SM_TOTAL);

    // 1) weight conversions (tiny)
    {
        int nblk = (N4WU + N4WD + 255) / 256;
        conv_w_kernel<<<nblk, 256>>>((const float4*)W_up, (const float4*)W_down);
    }

    // 2) KNN (32KB static smem -> high occupancy)
    dim3 gk(N_UP / 256, BATCH);
    knn_kernel<<<gk, 256>>>(up_points, down_points);

    // 3) down GEMM (A = down_features fp32, converted in-kernel)
    dim3 g1(C_OUT / 128, M_DN / 128);   // (4, 128)
    gemm1_kernel<<<g1, 256, SM_TOTAL>>>(down_features, b_down);

    // 4) fused output GEMM + interpolation (A = up_features fp32)
    dim3 g2(C_OUT / 128, M_UP / 128);   // (4, 512)
    gemm2_kernel<<<g2, 256, SM_TOTAL>>>(up_features, b_up, out);
}